// round 1
// baseline (speedup 1.0000x reference)
#include <cuda_runtime.h>

#define DM    64
#define NPTS  1323
#define NTHR  256

__global__ __launch_bounds__(NTHR) void mvn_profile_kernel(
    const float* __restrict__ rep,
    const float* __restrict__ dxyz,
    const float* __restrict__ Wm,
    const float* __restrict__ bm,
    const float* __restrict__ Ws,
    const float* __restrict__ bs,
    float* __restrict__ out)
{
    __shared__ float srep[DM];
    __shared__ float sp[10];   // 0..2: means, 3..8: chol params, 9: C

    const int b = blockIdx.x;
    const int t = threadIdx.x;

    if (t < DM) srep[t] = rep[(size_t)b * DM + t];
    __syncthreads();

    // 9 dot products: 3 for means, 6 for scale logits -> sigmoid
    if (t < 9) {
        const float* w = (t < 3) ? (Wm + t * DM) : (Ws + (t - 3) * DM);
        float acc = (t < 3) ? bm[t] : bs[t - 3];
        #pragma unroll
        for (int i = 0; i < DM; i++)
            acc = fmaf(srep[i], __ldg(w + i), acc);
        if (t >= 3)
            acc = 1.0f / (1.0f + expf(-acc));   // sigmoid (accurate; per-row only)
        sp[t] = acc;
    }
    __syncthreads();

    if (t == 0) {
        // softplus of sigmoid outputs for diagonal terms
        float L00 = log1pf(expf(sp[3]));
        float L10 = sp[4];
        float L11 = log1pf(expf(sp[5]));
        float L20 = sp[6];
        float L21 = sp[7];
        float L22 = log1pf(expf(sp[8]));
        sp[3] = 1.0f / L00;
        sp[4] = L10;
        sp[5] = 1.0f / L11;
        sp[6] = L20;
        sp[7] = L21;
        sp[8] = 1.0f / L22;
        // exp(-logdet - 1.5*log(2pi)) = 1 / (L00*L11*L22 * (2pi)^1.5)
        const float TWO_PI_1P5 = 15.749609945722419f;
        sp[9] = 1.0f / (L00 * L11 * L22 * TWO_PI_1P5);
    }
    __syncthreads();

    const float m0 = sp[0], m1 = sp[1], m2 = sp[2];
    const float iL00 = sp[3], L10 = sp[4], iL11 = sp[5];
    const float L20 = sp[6], L21 = sp[7], iL22 = sp[8];
    const float C = sp[9];

    const float* __restrict__ dp = dxyz + (size_t)b * (NPTS * 3);
    float* __restrict__ op = out + (size_t)b * NPTS;

    #pragma unroll 3
    for (int p = t; p < NPTS; p += NTHR) {
        float d0 = dp[3 * p + 0] - m0;
        float d1 = dp[3 * p + 1] - m1;
        float d2 = dp[3 * p + 2] - m2;
        float z0 = d0 * iL00;
        float z1 = (d1 - L10 * z0) * iL11;
        float z2 = fmaf(-L21, z1, fmaf(-L20, z0, d2)) * iL22;
        float maha = fmaf(z0, z0, fmaf(z1, z1, z2 * z2));
        op[p] = C * __expf(-0.5f * maha);
    }
}

extern "C" void kernel_launch(void* const* d_in, const int* in_sizes, int n_in,
                              void* d_out, int out_size)
{
    const float* rep  = (const float*)d_in[0];
    const float* dxyz = (const float*)d_in[1];
    const float* Wm   = (const float*)d_in[2];
    const float* bm   = (const float*)d_in[3];
    const float* Ws   = (const float*)d_in[4];
    const float* bs   = (const float*)d_in[5];
    // d_in[6] = num_planes (always 3 for this shape) — unused

    float* out = (float*)d_out;

    const int nrows = in_sizes[0] / DM;   // 16384
    mvn_profile_kernel<<<nrows, NTHR>>>(rep, dxyz, Wm, bm, Ws, bs, out);
}

// round 2
// speedup vs baseline: 1.3905x; 1.3905x over previous
#include <cuda_runtime.h>

#define DM        64
#define NPTS      1323
#define RPB       4                 // rows per block
#define NTHR      256
#define GROUP_PTS (NPTS * RPB)      // 5292
#define SLOTS     (GROUP_PTS / 4)   // 1323 (exact, no tail)
#define PSTRIDE   11                // param smem stride (conflict-free across rows)

// one point through the inverse-Cholesky transform + gaussian
__device__ __forceinline__ float mvn_pt(float d0, float d1, float d2,
                                        const float* __restrict__ q)
{
    d0 -= q[0];
    d1 -= q[1];
    d2 -= q[2];
    float z0 = d0 * q[3];
    float z1 = (d1 - q[4] * z0) * q[5];
    float z2 = fmaf(-q[7], z1, fmaf(-q[6], z0, d2)) * q[8];
    float maha = fmaf(z0, z0, fmaf(z1, z1, z2 * z2));
    return q[9] * __expf(-0.5f * maha);
}

__global__ __launch_bounds__(NTHR) void mvn_profile_kernel(
    const float* __restrict__ rep,
    const float* __restrict__ dxyz,
    const float* __restrict__ Wm,
    const float* __restrict__ bm,
    const float* __restrict__ Ws,
    const float* __restrict__ bs,
    float* __restrict__ out)
{
    __shared__ float srep[RPB * DM];          // 4 rep rows
    __shared__ float sp[RPB * PSTRIDE];       // per-row params: m0..2, iL00,L10,iL11,L20,L21,iL22, C

    const int t = threadIdx.x;
    const int g = blockIdx.x;                 // group of 4 rows

    // stage 4 rep rows (256 floats, one per thread)
    srep[t] = rep[(size_t)g * (RPB * DM) + t];
    __syncthreads();

    // 36 dot products: rows 0..3 x components 0..8
    if (t < RPB * 9) {
        const int r = t / 9, c = t % 9;
        const float* w = (c < 3) ? (Wm + c * DM) : (Ws + (c - 3) * DM);
        float acc = (c < 3) ? bm[c] : bs[c - 3];
        #pragma unroll
        for (int i = 0; i < DM; i++)
            acc = fmaf(srep[r * DM + i], __ldg(w + i), acc);
        if (c >= 3)
            acc = 1.0f / (1.0f + expf(-acc));   // sigmoid (per-row, accurate)
        sp[r * PSTRIDE + c] = acc;
    }
    __syncthreads();

    // finalize per-row params (softplus diag, inverses, normalization const)
    if (t < RPB) {
        float* q = sp + t * PSTRIDE;
        float L00 = log1pf(expf(q[3]));
        float L11 = log1pf(expf(q[5]));
        float L22 = log1pf(expf(q[8]));
        q[3] = 1.0f / L00;
        q[5] = 1.0f / L11;
        q[8] = 1.0f / L22;
        const float TWO_PI_1P5 = 15.749609945722419f;   // (2*pi)^1.5
        q[9] = 1.0f / (L00 * L11 * L22 * TWO_PI_1P5);
    }
    __syncthreads();

    // fully aligned group bases: 4*15876B and 4*5292B are both 16B multiples
    const float4* __restrict__ dp4 =
        (const float4*)(dxyz + (size_t)g * (GROUP_PTS * 3));
    float4* __restrict__ op4 = (float4*)(out + (size_t)g * GROUP_PTS);

    #pragma unroll 2
    for (int s = t; s < SLOTS; s += NTHR) {
        float4 a = dp4[3 * s + 0];
        float4 b = dp4[3 * s + 1];
        float4 c = dp4[3 * s + 2];
        // points: p0=(a.x,a.y,a.z) p1=(a.w,b.x,b.y) p2=(b.z,b.w,c.x) p3=(c.y,c.z,c.w)
        const int p0 = 4 * s;
        const int r0 = (p0 * 12682) >> 24;          // exact p/1323 for p<5292
        const int r3 = ((p0 + 3) * 12682) >> 24;

        float4 res;
        if (r0 == r3) {
            // fast path (99.8%): all 4 points in one row — params in registers
            float q[10];
            const float* qs = sp + r0 * PSTRIDE;
            #pragma unroll
            for (int k = 0; k < 10; k++) q[k] = qs[k];
            res.x = mvn_pt(a.x, a.y, a.z, q);
            res.y = mvn_pt(a.w, b.x, b.y, q);
            res.z = mvn_pt(b.z, b.w, c.x, q);
            res.w = mvn_pt(c.y, c.z, c.w, q);
        } else {
            // row boundary inside this slot — per-point row lookup
            const int r1 = ((p0 + 1) * 12682) >> 24;
            const int r2 = ((p0 + 2) * 12682) >> 24;
            res.x = mvn_pt(a.x, a.y, a.z, sp + r0 * PSTRIDE);
            res.y = mvn_pt(a.w, b.x, b.y, sp + r1 * PSTRIDE);
            res.z = mvn_pt(b.z, b.w, c.x, sp + r2 * PSTRIDE);
            res.w = mvn_pt(c.y, c.z, c.w, sp + r3 * PSTRIDE);
        }
        op4[s] = res;
    }
}

extern "C" void kernel_launch(void* const* d_in, const int* in_sizes, int n_in,
                              void* d_out, int out_size)
{
    const float* rep  = (const float*)d_in[0];
    const float* dxyz = (const float*)d_in[1];
    const float* Wm   = (const float*)d_in[2];
    const float* bm   = (const float*)d_in[3];
    const float* Ws   = (const float*)d_in[4];
    const float* bs   = (const float*)d_in[5];
    // d_in[6] = num_planes (fixed 3) — unused

    float* out = (float*)d_out;

    const int nrows  = in_sizes[0] / DM;     // 16384
    const int groups = nrows / RPB;          // 4096
    mvn_profile_kernel<<<groups, NTHR>>>(rep, dxyz, Wm, bm, Ws, bs, out);
}

// round 3
// speedup vs baseline: 1.5214x; 1.0941x over previous
#include <cuda_runtime.h>

#define DM        64
#define NPTS      1323
#define MAXROWS   16384
#define NTHR      256

// param records: 12 floats per row (3 float4): m0,m1,m2,iL00 | L10,iL11,L20,L21 | iL22,C,pad,pad
__device__ float g_params[MAXROWS * 12];

// ---------------- Kernel A: per-row parameters (one warp per row) ----------------
__global__ __launch_bounds__(NTHR) void mvn_params_kernel(
    const float* __restrict__ rep,
    const float* __restrict__ Wm,
    const float* __restrict__ bm,
    const float* __restrict__ Ws,
    const float* __restrict__ bs,
    int nrows)
{
    const int warp = (blockIdx.x * NTHR + threadIdx.x) >> 5;
    const int lane = threadIdx.x & 31;
    if (warp >= nrows) return;

    const float2 v = ((const float2*)(rep + (size_t)warp * DM))[lane];

    float dots[9];
    #pragma unroll
    for (int c = 0; c < 9; c++) {
        const float* w = (c < 3) ? (Wm + c * DM) : (Ws + (c - 3) * DM);
        const float2 wv = ((const float2*)w)[lane];
        float partial = fmaf(v.x, wv.x, v.y * wv.y);
        #pragma unroll
        for (int off = 16; off > 0; off >>= 1)
            partial += __shfl_xor_sync(0xFFFFFFFFu, partial, off);
        dots[c] = partial;
    }

    if (lane == 0) {
        float m0 = dots[0] + bm[0];
        float m1 = dots[1] + bm[1];
        float m2 = dots[2] + bm[2];
        float s[6];
        #pragma unroll
        for (int i = 0; i < 6; i++)
            s[i] = 1.0f / (1.0f + expf(-(dots[3 + i] + bs[i])));   // sigmoid
        float L00 = log1pf(expf(s[0]));
        float L10 = s[1];
        float L11 = log1pf(expf(s[2]));
        float L20 = s[3];
        float L21 = s[4];
        float L22 = log1pf(expf(s[5]));
        const float TWO_PI_1P5 = 15.749609945722419f;   // (2*pi)^1.5
        float C = 1.0f / (L00 * L11 * L22 * TWO_PI_1P5);

        float4* q = (float4*)(g_params + warp * 12);
        q[0] = make_float4(m0, m1, m2, 1.0f / L00);
        q[1] = make_float4(L10, 1.0f / L11, L20, L21);
        q[2] = make_float4(1.0f / L22, C, 0.0f, 0.0f);
    }
}

// one point through the inverse-Cholesky transform + gaussian
__device__ __forceinline__ float mvn_pt(float d0, float d1, float d2,
                                        float4 qa, float4 qb, float4 qc)
{
    d0 -= qa.x;
    d1 -= qa.y;
    d2 -= qa.z;
    float z0 = d0 * qa.w;
    float z1 = (d1 - qb.x * z0) * qb.y;
    float z2 = fmaf(-qb.w, z1, fmaf(-qb.z, z0, d2)) * qc.x;
    float maha = fmaf(z0, z0, fmaf(z1, z1, z2 * z2));
    return qc.y * __expf(-0.5f * maha);
}

// ---------------- Kernel B: pure streaming, one slot (4 points) per thread ----------------
__global__ __launch_bounds__(NTHR) void mvn_stream_kernel(
    const float* __restrict__ dxyz,
    float* __restrict__ out)
{
    const unsigned s = blockIdx.x * NTHR + threadIdx.x;   // slot index, grid sized exactly
    const unsigned p0 = 4u * s;

    // exact p/1323 for p < ~2e9 (magic: ceil(2^40/1323) = 831074549, err 551)
    const unsigned r0 = (unsigned)(((unsigned long long)p0 * 831074549ull) >> 40);
    const unsigned r3 = (unsigned)(((unsigned long long)(p0 + 3u) * 831074549ull) >> 40);

    const float4* __restrict__ dp4 = (const float4*)dxyz + 3u * (size_t)s;
    const float4 a = __ldcs(dp4 + 0);
    const float4 b = __ldcs(dp4 + 1);
    const float4 c = __ldcs(dp4 + 2);
    // points: p0=(a.x,a.y,a.z) p1=(a.w,b.x,b.y) p2=(b.z,b.w,c.x) p3=(c.y,c.z,c.w)

    const float4* __restrict__ P = (const float4*)g_params;
    float4 qa = __ldg(P + 3u * r0 + 0);
    float4 qb = __ldg(P + 3u * r0 + 1);
    float4 qc = __ldg(P + 3u * r0 + 2);

    float4 res;
    if (r0 == r3) {
        // fast path (99.7%)
        res.x = mvn_pt(a.x, a.y, a.z, qa, qb, qc);
        res.y = mvn_pt(a.w, b.x, b.y, qa, qb, qc);
        res.z = mvn_pt(b.z, b.w, c.x, qa, qb, qc);
        res.w = mvn_pt(c.y, c.z, c.w, qa, qb, qc);
    } else {
        // slot crosses a row boundary: points >= E use row r3's params
        const unsigned E = (r0 + 1u) * (unsigned)NPTS;
        const float4 qa2 = __ldg(P + 3u * r3 + 0);
        const float4 qb2 = __ldg(P + 3u * r3 + 1);
        const float4 qc2 = __ldg(P + 3u * r3 + 2);
        res.x = (p0 + 0 < E) ? mvn_pt(a.x, a.y, a.z, qa, qb, qc)
                             : mvn_pt(a.x, a.y, a.z, qa2, qb2, qc2);
        res.y = (p0 + 1 < E) ? mvn_pt(a.w, b.x, b.y, qa, qb, qc)
                             : mvn_pt(a.w, b.x, b.y, qa2, qb2, qc2);
        res.z = (p0 + 2 < E) ? mvn_pt(b.z, b.w, c.x, qa, qb, qc)
                             : mvn_pt(b.z, b.w, c.x, qa2, qb2, qc2);
        res.w = (p0 + 3 < E) ? mvn_pt(c.y, c.z, c.w, qa, qb, qc)
                             : mvn_pt(c.y, c.z, c.w, qa2, qb2, qc2);
    }

    __stcs((float4*)out + s, res);
}

extern "C" void kernel_launch(void* const* d_in, const int* in_sizes, int n_in,
                              void* d_out, int out_size)
{
    const float* rep  = (const float*)d_in[0];
    const float* dxyz = (const float*)d_in[1];
    const float* Wm   = (const float*)d_in[2];
    const float* bm   = (const float*)d_in[3];
    const float* Ws   = (const float*)d_in[4];
    const float* bs   = (const float*)d_in[5];
    // d_in[6] = num_planes (fixed 3) — unused

    float* out = (float*)d_out;

    int nrows = in_sizes[0] / DM;          // 16384
    if (nrows > MAXROWS) nrows = MAXROWS;

    // Kernel A: 8 rows per 256-thread block
    const int blkA = (nrows * 32 + NTHR - 1) / NTHR;
    mvn_params_kernel<<<blkA, NTHR>>>(rep, Wm, bm, Ws, bs, nrows);

    // Kernel B: one slot (4 points) per thread; slots = nrows*1323/4, divisible by 256
    const unsigned total_slots = (unsigned)nrows * NPTS / 4u;
    const unsigned blkB = (total_slots + NTHR - 1) / NTHR;
    mvn_stream_kernel<<<blkB, NTHR>>>(dxyz, out);
}